// round 1
// baseline (speedup 1.0000x reference)
#include <cuda_runtime.h>
#include <cuda_bf16.h>

#define MAXN 50000
#define MAXE 600000
#define L 128
#define INF 7

// ---------------- device scratch (no allocations allowed) ----------------
__device__ float g_h[MAXN * L];
__device__ float g_t0[MAXN * L];
__device__ float g_t1[MAXN * L];
__device__ float g_inv_s[MAXN];
__device__ float g_inv_r[MAXN];
__device__ int   g_deg_s[MAXN];
__device__ int   g_deg_r[MAXN];
__device__ int   g_row[MAXN];     // exclusive prefix sum of g_deg_r
__device__ int   g_fill[MAXN];
__device__ int   g_csr_sender[MAXE];

// ---------------- setup kernels ----------------
__global__ void zero_kernel(int n) {
    for (int i = blockIdx.x * blockDim.x + threadIdx.x; i < n; i += gridDim.x * blockDim.x) {
        g_deg_s[i] = 0; g_deg_r[i] = 0; g_fill[i] = 0;
    }
}

__global__ void degree_kernel(const int* __restrict__ senders,
                              const int* __restrict__ receivers, int e) {
    for (int t = blockIdx.x * blockDim.x + threadIdx.x; t < e; t += gridDim.x * blockDim.x) {
        atomicAdd(&g_deg_s[senders[t]], 1);
        atomicAdd(&g_deg_r[receivers[t]], 1);
    }
}

__global__ void inv_kernel(int n) {
    for (int i = blockIdx.x * blockDim.x + threadIdx.x; i < n; i += gridDim.x * blockDim.x) {
        g_inv_s[i] = rsqrtf(fmaxf((float)g_deg_s[i], 1.0f));
        g_inv_r[i] = rsqrtf(fmaxf((float)g_deg_r[i], 1.0f));
    }
}

// Single-block exclusive prefix scan of g_deg_r -> g_row. 1024 threads,
// 4 elements/thread per tile (tile = 4096), warp-shfl based (2 barriers/tile).
__global__ void scan_kernel(int n) {
    __shared__ int shW[32];
    const int tid = threadIdx.x;
    const int lane = tid & 31, wid = tid >> 5;
    int carry = 0;
    for (int base = 0; base < n; base += 4096) {
        int idx = base + tid * 4;
        int v0 = (idx + 0 < n) ? g_deg_r[idx + 0] : 0;
        int v1 = (idx + 1 < n) ? g_deg_r[idx + 1] : 0;
        int v2 = (idx + 2 < n) ? g_deg_r[idx + 2] : 0;
        int v3 = (idx + 3 < n) ? g_deg_r[idx + 3] : 0;
        int s = v0 + v1 + v2 + v3;
        // inclusive warp scan of s
        int ws = s;
        #pragma unroll
        for (int off = 1; off < 32; off <<= 1) {
            int t = __shfl_up_sync(0xFFFFFFFF, ws, off);
            if (lane >= off) ws += t;
        }
        if (lane == 31) shW[wid] = ws;
        __syncthreads();
        if (wid == 0) {
            int x = shW[lane];
            #pragma unroll
            for (int off = 1; off < 32; off <<= 1) {
                int t = __shfl_up_sync(0xFFFFFFFF, x, off);
                if (lane >= off) x += t;
            }
            shW[lane] = x;   // inclusive warp totals
        }
        __syncthreads();
        int warp_off = (wid == 0) ? 0 : shW[wid - 1];
        int tile_total = shW[31];
        int te = carry + warp_off + (ws - s);     // exclusive offset of this thread
        if (idx + 0 < n) g_row[idx + 0] = te;
        if (idx + 1 < n) g_row[idx + 1] = te + v0;
        if (idx + 2 < n) g_row[idx + 2] = te + v0 + v1;
        if (idx + 3 < n) g_row[idx + 3] = te + v0 + v1 + v2;
        carry += tile_total;
        __syncthreads();
    }
}

__global__ void fill_kernel(const int* __restrict__ senders,
                            const int* __restrict__ receivers, int e) {
    for (int t = blockIdx.x * blockDim.x + threadIdx.x; t < e; t += gridDim.x * blockDim.x) {
        int r = receivers[t];
        int p = g_row[r] + atomicAdd(&g_fill[r], 1);
        g_csr_sender[p] = senders[t];
    }
}

// ---------------- embed: h = nodes @ W_embed + b ----------------
__global__ void embed_kernel(const float* __restrict__ nodes,
                             const float* __restrict__ We,
                             const float* __restrict__ be, int n) {
    int i = blockIdx.x;
    if (i >= n) return;
    int j = threadIdx.x;            // 128
    float s = be[j];
    #pragma unroll
    for (int k = 0; k < INF; k++) s = fmaf(nodes[i * INF + k], We[k * L + j], s);
    g_h[i * L + j] = s;
}

// ---------------- MLP layer: out = relu(in @ W + b), [n,128] @ [128,128] ----
// block: 256 threads = (tx 0..31 feature-group, ty 0..7 node-group)
// 64 nodes/block, thread computes 8 nodes x 4 feats.
__global__ void __launch_bounds__(256) mlp_kernel(const float* __restrict__ in,
                                                  const float* __restrict__ W,
                                                  const float* __restrict__ b,
                                                  float* __restrict__ out, int n) {
    __shared__ float sh[64 * L];
    const int tid = threadIdx.x;
    const int node0 = blockIdx.x * 64;
    const float4* in4 = (const float4*)in;
    float4* sh4 = (float4*)sh;
    #pragma unroll
    for (int it = 0; it < 8; it++) {
        int v = tid + it * 256;         // float4 index, row = v/32
        int row = v >> 5, c = v & 31;
        float4 val = make_float4(0.f, 0.f, 0.f, 0.f);
        if (node0 + row < n) val = in4[(size_t)(node0 + row) * 32 + c];
        sh4[v] = val;
    }
    __syncthreads();
    const int tx = tid & 31, ty = tid >> 5;
    float acc[8][4];
    #pragma unroll
    for (int i = 0; i < 8; i++) { acc[i][0]=0.f; acc[i][1]=0.f; acc[i][2]=0.f; acc[i][3]=0.f; }
    const float* shrow = sh + ty * 8 * L;
    #pragma unroll 4
    for (int k = 0; k < L; k++) {
        float4 w = __ldg((const float4*)&W[k * L + tx * 4]);
        #pragma unroll
        for (int i = 0; i < 8; i++) {
            float a = shrow[i * L + k];
            acc[i][0] = fmaf(a, w.x, acc[i][0]);
            acc[i][1] = fmaf(a, w.y, acc[i][1]);
            acc[i][2] = fmaf(a, w.z, acc[i][2]);
            acc[i][3] = fmaf(a, w.w, acc[i][3]);
        }
    }
    float4 bb = __ldg((const float4*)&b[tx * 4]);
    #pragma unroll
    for (int i = 0; i < 8; i++) {
        int node = node0 + ty * 8 + i;
        if (node < n) {
            float4 o;
            o.x = fmaxf(acc[i][0] + bb.x, 0.f);
            o.y = fmaxf(acc[i][1] + bb.y, 0.f);
            o.z = fmaxf(acc[i][2] + bb.z, 0.f);
            o.w = fmaxf(acc[i][3] + bb.w, 0.f);
            *(float4*)&out[(size_t)node * L + tx * 4] = o;
        }
    }
}

// ---------------- aggregation + skip + layernorm (warp per node) ----------
__global__ void agg_ln_kernel(const float* __restrict__ x,
                              const float* __restrict__ scale,
                              const float* __restrict__ bias, int n) {
    const int lane = threadIdx.x & 31;
    const int node = blockIdx.x * (blockDim.x >> 5) + (threadIdx.x >> 5);
    if (node >= n) return;
    const int start = g_row[node];
    const int deg = g_deg_r[node];
    float a0 = 0.f, a1 = 0.f, a2 = 0.f, a3 = 0.f;
    for (int j = 0; j < deg; j++) {
        int s = g_csr_sender[start + j];
        float ws = g_inv_s[s];
        float4 xv = *(const float4*)&x[(size_t)s * L + lane * 4];
        a0 = fmaf(ws, xv.x, a0);
        a1 = fmaf(ws, xv.y, a1);
        a2 = fmaf(ws, xv.z, a2);
        a3 = fmaf(ws, xv.w, a3);
    }
    float wr = g_inv_r[node];
    float4 hv = *(const float4*)&g_h[(size_t)node * L + lane * 4];
    float v0 = hv.x + wr * a0;
    float v1 = hv.y + wr * a1;
    float v2 = hv.z + wr * a2;
    float v3 = hv.w + wr * a3;
    float sum = v0 + v1 + v2 + v3;
    float sq  = v0*v0 + v1*v1 + v2*v2 + v3*v3;
    #pragma unroll
    for (int off = 16; off >= 1; off >>= 1) {
        sum += __shfl_xor_sync(0xFFFFFFFF, sum, off);
        sq  += __shfl_xor_sync(0xFFFFFFFF, sq, off);
    }
    float mean = sum * (1.0f / L);
    float var  = sq * (1.0f / L) - mean * mean;
    float rstd = rsqrtf(var + 1e-6f);
    int f = lane * 4;
    float4 o;
    o.x = (v0 - mean) * rstd * scale[f + 0] + bias[f + 0];
    o.y = (v1 - mean) * rstd * scale[f + 1] + bias[f + 1];
    o.z = (v2 - mean) * rstd * scale[f + 2] + bias[f + 2];
    o.w = (v3 - mean) * rstd * scale[f + 3] + bias[f + 3];
    *(float4*)&g_h[(size_t)node * L + lane * 4] = o;
}

// ---------------- decode: out = h @ W_dec + b_dec (warp per node) ---------
__global__ void decode_kernel(const float* __restrict__ Wd,
                              const float* __restrict__ bd,
                              float* __restrict__ out, int n) {
    const int lane = threadIdx.x & 31;
    const int node = blockIdx.x * (blockDim.x >> 5) + (threadIdx.x >> 5);
    if (node >= n) return;
    float4 hv = *(const float4*)&g_h[(size_t)node * L + lane * 4];
    int k = lane * 4;
    float r[INF];
    #pragma unroll
    for (int j = 0; j < INF; j++) {
        float p = hv.x * Wd[(k + 0) * INF + j]
                + hv.y * Wd[(k + 1) * INF + j]
                + hv.z * Wd[(k + 2) * INF + j]
                + hv.w * Wd[(k + 3) * INF + j];
        #pragma unroll
        for (int off = 16; off >= 1; off >>= 1) p += __shfl_xor_sync(0xFFFFFFFF, p, off);
        r[j] = p;
    }
    if (lane < INF) out[node * INF + lane] = r[lane] + bd[lane];
}

// ---------------- launch ----------------
extern "C" void kernel_launch(void* const* d_in, const int* in_sizes, int n_in,
                              void* d_out, int out_size) {
    const float* nodes     = (const float*)d_in[0];
    const int*   senders   = (const int*)d_in[1];
    const int*   receivers = (const int*)d_in[2];
    const float* W_embed   = (const float*)d_in[3];
    const float* b_embed   = (const float*)d_in[4];
    const float* mlp_W     = (const float*)d_in[5];
    const float* mlp_b     = (const float*)d_in[6];
    const float* ln_scale  = (const float*)d_in[7];
    const float* ln_bias   = (const float*)d_in[8];
    const float* W_dec     = (const float*)d_in[9];
    const float* b_dec     = (const float*)d_in[10];
    float* out = (float*)d_out;

    const int n = in_sizes[0] / INF;
    const int e = in_sizes[1];

    zero_kernel<<<256, 256>>>(n);
    degree_kernel<<<(e + 255) / 256, 256>>>(senders, receivers, e);
    inv_kernel<<<(n + 255) / 256, 256>>>(n);
    scan_kernel<<<1, 1024>>>(n);
    fill_kernel<<<(e + 255) / 256, 256>>>(senders, receivers, e);

    float* d_h; cudaGetSymbolAddress((void**)&d_h, g_h);
    float* d_t0; cudaGetSymbolAddress((void**)&d_t0, g_t0);
    float* d_t1; cudaGetSymbolAddress((void**)&d_t1, g_t1);

    embed_kernel<<<n, 128>>>(nodes, W_embed, b_embed, n);

    const int mlp_blocks = (n + 63) / 64;
    const int warp_blocks = (n + 7) / 8;   // 8 warps / 256-thread block
    for (int step = 0; step < 3; step++) {
        const float* W0 = mlp_W + (size_t)(step * 2 + 0) * L * L;
        const float* W1 = mlp_W + (size_t)(step * 2 + 1) * L * L;
        const float* b0 = mlp_b + (size_t)(step * 2 + 0) * L;
        const float* b1 = mlp_b + (size_t)(step * 2 + 1) * L;
        mlp_kernel<<<mlp_blocks, 256>>>(d_h, W0, b0, d_t0, n);
        mlp_kernel<<<mlp_blocks, 256>>>(d_t0, W1, b1, d_t1, n);
        agg_ln_kernel<<<warp_blocks, 256>>>(d_t1, ln_scale + step * L, ln_bias + step * L, n);
    }
    decode_kernel<<<warp_blocks, 256>>>(W_dec, b_dec, out, n);
}